// round 15
// baseline (speedup 1.0000x reference)
#include <cuda_runtime.h>
#include <math.h>

#define NE    14
#define NSV   256
#define NPVs  33
#define NPAIR 196
#define NORB  112
#define NFB   3

struct __align__(16) Smem {
    float2 svP[NE][NSV];         // packed (el0, el1)
    float  pv[2][NPAIR * NPVs];  // unpacked pair stream; reused as orbm
    float2 redP[4][NE][NSV];     // packed k-split partials; orbital reuses as [8][NE][NORB]
    float2 scrP[896];            // packed ext means; layer0 pin via float* view
    float  mumd[2][512];
    float  cm[2][NSV];
    float  pwS[1024];
    float  pbS[32];
    float  m0P[2][16];
    float  sin8[2][NE][8];
    float  env[2][NE];
    float  rl[2][NE][3];
    float  ldet[2][32];
    float  sgn[2][32];
};

union U64 { unsigned long long u; float2 f; };

__device__ __forceinline__ void ffma2(unsigned long long &d, unsigned long long a, unsigned long long b) {
    asm("fma.rn.f32x2 %0, %1, %2, %0;" : "+l"(d) : "l"(a), "l"(b));
}
__device__ __forceinline__ unsigned long long dup2(float x) {
    unsigned long long r;
    asm("mov.b64 %0, {%1, %1};" : "=l"(r) : "f"(x));
    return r;
}
__device__ __forceinline__ int swz(int c)  { return c ^ (c >> 5); }
__device__ __forceinline__ int swzo(int o) { return o ^ (o >> 5); }

__device__ __forceinline__ float fast_tanh(float x) {
    float e = __expf(2.0f * x);
    return 1.0f - __fdividef(2.0f, e + 1.0f);
}

__global__ void __launch_bounds__(512, 1)
ansatz_kernel(const float* __restrict__ r,
              const float* __restrict__ s_w0, const float* __restrict__ s_b0,
              const float* __restrict__ s_w,  const float* __restrict__ s_b,
              const float* __restrict__ p_w0, const float* __restrict__ p_b0,
              const float* __restrict__ p_w,  const float* __restrict__ p_b,
              const float* __restrict__ va_w, const float* __restrict__ va_b,
              const float* __restrict__ wu_w, const float* __restrict__ wu_b,
              const float* __restrict__ wd_w, const float* __restrict__ wd_b,
              const float* __restrict__ wf_w,
              float* __restrict__ out, int nb)
{
    extern __shared__ char smem_raw[];
    Smem& s = *reinterpret_cast<Smem*>(smem_raw);

    const int t    = threadIdx.x;
    const int lane = t & 31;
    const int wid  = t >> 5;
    const int b0   = blockIdx.x * 2;
    const float inv7 = 1.0f / 7.0f;

    const int tel = t >> 8;
    const int tc  = t & 255;

    float* scrF = (float*)s.scrP;   // layer0 view [el*896 + ...]

    // ---------------- Phase 0: geometry ----------------
    for (int q = t; q < 2 * NE * 3; q += 512) {
        int el = q / (NE * 3);
        int bel = b0 + el; if (bel >= nb) bel = nb - 1;
        ((float*)s.rl[el])[q - el * (NE * 3)] = r[bel * (NE * 3) + (q - el * (NE * 3))];
    }
    __syncthreads();

    if (t < 2 * NE) {
        int el = t / NE, e = t - el * NE;
        float x = s.rl[el][e][0], y = s.rl[el][e][1], z = s.rl[el][e][2];
        float ev = 0.f;
        #pragma unroll
        for (int a = 0; a < 2; ++a) {
            float dz = z - (a ? 1.4f : 0.0f);
            float len = sqrtf(x * x + y * y + dz * dz);
            s.sin8[el][e][a * 4 + 0] = x;
            s.sin8[el][e][a * 4 + 1] = y;
            s.sin8[el][e][a * 4 + 2] = dz;
            s.sin8[el][e][a * 4 + 3] = len;
            ev += __expf(-len);
        }
        s.env[el][e] = ev;
    }
    if (t < 2 * NPAIR) {
        int el = t / NPAIR, pr = t - el * NPAIR;
        int i = pr / 14, j = pr - i * 14;
        float dx = s.rl[el][j][0] - s.rl[el][i][0];
        float dy = s.rl[el][j][1] - s.rl[el][i][1];
        float dz = s.rl[el][j][2] - s.rl[el][i][2];
        float ax = dx, ay = dy, az = dz;
        if (i == j) { ax += 1.f; ay += 1.f; az += 1.f; }
        float len = sqrtf(ax * ax + ay * ay + az * az);
        scrF[el * 896 + pr * 4 + 0] = dx; scrF[el * 896 + pr * 4 + 1] = dy;
        scrF[el * 896 + pr * 4 + 2] = dz; scrF[el * 896 + pr * 4 + 3] = len;
    }
    __syncthreads();

    if (t < 32) {
        int el = t >> 4, q = t & 15;
        int k = q & 7, half = q >> 3;
        float su = 0.f;
        #pragma unroll
        for (int e = 0; e < 7; ++e) su += s.sin8[el][half * 7 + e][k];
        s.m0P[el][half * 8 + k] = su * inv7;
    }
    if (t >= 64 && t < 64 + 224) {
        int q2 = t - 64;
        int el = q2 / 112, q = q2 - el * 112;
        int dn = (q >= 56) ? 1 : 0;
        int qq = q - dn * 56;
        int e = qq >> 2, k = qq & 3;
        int i0 = dn ? 7 : 0;
        float su = 0.f;
        #pragma unroll
        for (int ii = 0; ii < 7; ++ii) su += scrF[el * 896 + ((i0 + ii) * 14 + e) * 4 + k];
        scrF[el * 896 + 784 + dn * 56 + e * 4 + k] = su * inv7;
    }
    __syncthreads();

    // ---------------- Layer 0 (fused: svP + mumd + cm init) ----------------
    {
        float pnew[32];
        const bool prow = (t < 2 * NPAIR);
        int pel = 0, pr = 0;
        if (prow) {
            pel = t / NPAIR; pr = t - pel * NPAIR;
            const float* pin = scrF + pel * 896 + pr * 4;
            float r0 = pin[0], r1 = pin[1], r2 = pin[2], r3 = pin[3];
            #pragma unroll
            for (int c2 = 0; c2 < 32; ++c2) {
                float v = p_b0[c2]
                        + r0 * p_w0[0 * 32 + c2] + r1 * p_w0[1 * 32 + c2]
                        + r2 * p_w0[2 * 32 + c2] + r3 * p_w0[3 * 32 + c2];
                pnew[c2] = fast_tanh(v);
            }
        }
        float cm0 = s_b0[tc];
        #pragma unroll
        for (int k = 0; k < 8; ++k)
            cm0 += s.m0P[tel][k] * s_w0[(8 + k) * 256 + tc] + s.m0P[tel][8 + k] * s_w0[(16 + k) * 256 + tc];
        float acc[NE];
        #pragma unroll
        for (int e = 0; e < NE; ++e) acc[e] = cm0;
        #pragma unroll
        for (int k = 0; k < 8; ++k) {
            float w = s_w0[k * 256 + tc];
            #pragma unroll
            for (int e = 0; e < NE; ++e) acc[e] += s.sin8[tel][e][k] * w;
        }
        const float* pu0 = scrF + tel * 896 + 784;
        const float* pd0 = scrF + tel * 896 + 840;
        #pragma unroll
        for (int k = 0; k < 4; ++k) {
            float wuv = s_w0[(24 + k) * 256 + tc];
            float wdv = s_w0[(28 + k) * 256 + tc];
            #pragma unroll
            for (int e = 0; e < NE; ++e)
                acc[e] += pu0[e * 4 + k] * wuv + pd0[e * 4 + k] * wdv;
        }
        float su = 0.f, sd = 0.f;
        #pragma unroll
        for (int e = 0; e < NE; ++e) {
            float v = fast_tanh(acc[e]);
            ((float*)&s.svP[e][tc])[tel] = v;
            if (e < 7) su += v; else sd += v;
        }
        s.mumd[tel][tc]       = su * inv7;
        s.mumd[tel][256 + tc] = sd * inv7;
        s.cm[tel][swz(tc)]    = s_b[tc];
        if (prow) {
            #pragma unroll
            for (int c2 = 0; c2 < 32; ++c2) s.pv[pel][pr * NPVs + c2] = pnew[c2];
        }
    }
    __syncthreads();

    // ---------------- prep il=0: packed scr means + pwS ----------------
    for (int idx = t; idx < 896; idx += 512) {
        int dn = idx / 448, q = idx - dn * 448;
        int e = q >> 5, k = q & 31;
        int i0 = dn * 7;
        float s0 = 0.f, s1 = 0.f;
        #pragma unroll
        for (int ii = 0; ii < 7; ++ii) {
            int off = ((i0 + ii) * 14 + e) * NPVs + k;
            s0 += s.pv[0][off];
            s1 += s.pv[1][off];
        }
        s.scrP[idx] = make_float2(s0 * inv7, s1 * inv7);
    }
    #pragma unroll
    for (int idx = t; idx < 1024; idx += 512) s.pwS[idx] = p_w[idx];
    if (t < 32) s.pbS[t] = p_b[t];
    __syncthreads();

    // ---------------- FB layers + final va ----------------
    for (int il = 0; il <= NFB; ++il) {
        const bool last = (il == NFB);
        const float* WL = last ? va_w : (s_w + il * (832 * 256));

        // (b) pair GEMM — one thread = one pair row, both elements share weight broadcasts
        if (!last && t < NPAIR) {
            const int pr = t;
            unsigned long long o0[16], o1[16];
            const ulonglong2* pb2 = (const ulonglong2*)s.pbS;
            #pragma unroll
            for (int q = 0; q < 8; ++q) {
                ulonglong2 bv = pb2[q];
                o0[2 * q] = bv.x; o0[2 * q + 1] = bv.y;
                o1[2 * q] = bv.x; o1[2 * q + 1] = bv.y;
            }
            #pragma unroll 4
            for (int k = 0; k < 32; ++k) {
                unsigned long long r0 = dup2(s.pv[0][pr * NPVs + k]);
                unsigned long long r1 = dup2(s.pv[1][pr * NPVs + k]);
                const ulonglong2* w2 = (const ulonglong2*)(s.pwS + k * 32);
                #pragma unroll
                for (int q = 0; q < 8; ++q) {
                    ulonglong2 wv = w2[q];
                    ffma2(o0[2 * q],     r0, wv.x);
                    ffma2(o0[2 * q + 1], r0, wv.y);
                    ffma2(o1[2 * q],     r1, wv.x);
                    ffma2(o1[2 * q + 1], r1, wv.y);
                }
            }
            #pragma unroll
            for (int q = 0; q < 16; ++q) {
                U64 u0; u0.u = o0[q];
                U64 u1; u1.u = o1[q];
                s.pv[0][pr * NPVs + 2 * q]     = fast_tanh(u0.f.x) + s.pv[0][pr * NPVs + 2 * q];
                s.pv[0][pr * NPVs + 2 * q + 1] = fast_tanh(u0.f.y) + s.pv[0][pr * NPVs + 2 * q + 1];
                s.pv[1][pr * NPVs + 2 * q]     = fast_tanh(u1.f.x) + s.pv[1][pr * NPVs + 2 * q];
                s.pv[1][pr * NPVs + 2 * q + 1] = fast_tanh(u1.f.y) + s.pv[1][pr * NPVs + 2 * q + 1];
            }
        }

        // (d) main electron GEMM: el-packed activations, weight-dups only
        {
            const int kh  = wid & 3;
            const int ch  = (wid >> 2) & 1;
            const int eh2 = wid >> 3;
            const int e0  = eh2 * 7;
            const int c0  = ch * 128 + lane * 4;
            unsigned long long acc[7][4];
            #pragma unroll
            for (int i = 0; i < 7; ++i)
                #pragma unroll
                for (int c = 0; c < 4; ++c) acc[i][c] = 0ull;

            const int kb = kh * 64;
            const float* wpm = WL + kb * 256 + c0;
            float4 n0 = *(const float4*)(wpm);
            float4 n1 = *(const float4*)(wpm + 256);
            float4 n2 = *(const float4*)(wpm + 512);
            float4 n3 = *(const float4*)(wpm + 768);

            for (int kk = 0; kk < 64; kk += 4) {
                const int k = kb + kk;
                unsigned long long d00 = dup2(n0.x), d01 = dup2(n0.y), d02 = dup2(n0.z), d03 = dup2(n0.w);
                unsigned long long d10 = dup2(n1.x), d11 = dup2(n1.y), d12 = dup2(n1.z), d13 = dup2(n1.w);
                unsigned long long d20 = dup2(n2.x), d21 = dup2(n2.y), d22 = dup2(n2.z), d23 = dup2(n2.w);
                unsigned long long d30 = dup2(n3.x), d31 = dup2(n3.y), d32 = dup2(n3.z), d33 = dup2(n3.w);
                const float* wn = wpm + (kk + 4) * 256;   // row <= kb+67 <= 259 < 832
                n0 = *(const float4*)(wn);
                n1 = *(const float4*)(wn + 256);
                n2 = *(const float4*)(wn + 512);
                n3 = *(const float4*)(wn + 768);
                #pragma unroll
                for (int i = 0; i < 7; ++i) {
                    ulonglong2 A = *(const ulonglong2*)&s.svP[e0 + i][k];
                    ulonglong2 B = *(const ulonglong2*)&s.svP[e0 + i][k + 2];
                    ffma2(acc[i][0], A.x, d00); ffma2(acc[i][1], A.x, d01);
                    ffma2(acc[i][2], A.x, d02); ffma2(acc[i][3], A.x, d03);
                    ffma2(acc[i][0], A.y, d10); ffma2(acc[i][1], A.y, d11);
                    ffma2(acc[i][2], A.y, d12); ffma2(acc[i][3], A.y, d13);
                    ffma2(acc[i][0], B.x, d20); ffma2(acc[i][1], B.x, d21);
                    ffma2(acc[i][2], B.x, d22); ffma2(acc[i][3], B.x, d23);
                    ffma2(acc[i][0], B.y, d30); ffma2(acc[i][1], B.y, d31);
                    ffma2(acc[i][2], B.y, d32); ffma2(acc[i][3], B.y, d33);
                }
            }
            // ext rows: kh handles k in [kh*8, kh*8+8)
            #pragma unroll
            for (int blk = 0; blk < 2; ++blk) {
                const int rowb = 768 + blk * 32;
                const int scrb = blk * 448;
                #pragma unroll
                for (int kk = 0; kk < 8; kk += 4) {
                    const int k = kh * 8 + kk;
                    const float* wp = WL + (rowb + k) * 256 + c0;
                    float4 w0 = *(const float4*)(wp);
                    float4 w1 = *(const float4*)(wp + 256);
                    float4 w2 = *(const float4*)(wp + 512);
                    float4 w3 = *(const float4*)(wp + 768);
                    unsigned long long d00 = dup2(w0.x), d01 = dup2(w0.y), d02 = dup2(w0.z), d03 = dup2(w0.w);
                    unsigned long long d10 = dup2(w1.x), d11 = dup2(w1.y), d12 = dup2(w1.z), d13 = dup2(w1.w);
                    unsigned long long d20 = dup2(w2.x), d21 = dup2(w2.y), d22 = dup2(w2.z), d23 = dup2(w2.w);
                    unsigned long long d30 = dup2(w3.x), d31 = dup2(w3.y), d32 = dup2(w3.z), d33 = dup2(w3.w);
                    #pragma unroll
                    for (int i = 0; i < 7; ++i) {
                        const float2* sp = &s.scrP[scrb + (e0 + i) * 32 + k];
                        ulonglong2 A = *(const ulonglong2*)(sp);
                        ulonglong2 B = *(const ulonglong2*)(sp + 2);
                        ffma2(acc[i][0], A.x, d00); ffma2(acc[i][1], A.x, d01);
                        ffma2(acc[i][2], A.x, d02); ffma2(acc[i][3], A.x, d03);
                        ffma2(acc[i][0], A.y, d10); ffma2(acc[i][1], A.y, d11);
                        ffma2(acc[i][2], A.y, d12); ffma2(acc[i][3], A.y, d13);
                        ffma2(acc[i][0], B.x, d20); ffma2(acc[i][1], B.x, d21);
                        ffma2(acc[i][2], B.x, d22); ffma2(acc[i][3], B.x, d23);
                        ffma2(acc[i][0], B.y, d30); ffma2(acc[i][1], B.y, d31);
                        ffma2(acc[i][2], B.y, d32); ffma2(acc[i][3], B.y, d33);
                    }
                }
            }
            // store packed partials
            #pragma unroll
            for (int i = 0; i < 7; ++i) {
                U64 u0, u1, u2, u3;
                u0.u = acc[i][0]; u1.u = acc[i][1]; u2.u = acc[i][2]; u3.u = acc[i][3];
                *reinterpret_cast<float4*>(&s.redP[kh][e0 + i][c0])     = make_float4(u0.f.x, u0.f.y, u1.f.x, u1.f.y);
                *reinterpret_cast<float4*>(&s.redP[kh][e0 + i][c0 + 2]) = make_float4(u2.f.x, u2.f.y, u3.f.x, u3.f.y);
            }
        }

        // (c) cm rank-1 GEMM LAST — LDG bursts stagger against other warps' (d) tails
        {
            const int kb2 = wid * 32;
            const int c0m = lane * 8;
            unsigned long long ca[2][4];
            #pragma unroll
            for (int el = 0; el < 2; ++el)
                #pragma unroll
                for (int p = 0; p < 4; ++p) ca[el][p] = 0ull;

            const float* wpc = WL + (256 + kb2) * 256 + c0m;
            ulonglong2 nA0 = *(const ulonglong2*)(wpc);
            ulonglong2 nB0 = *(const ulonglong2*)(wpc + 4);
            ulonglong2 nA1 = *(const ulonglong2*)(wpc + 256);
            ulonglong2 nB1 = *(const ulonglong2*)(wpc + 260);
            ulonglong2 nA2 = *(const ulonglong2*)(wpc + 512);
            ulonglong2 nB2 = *(const ulonglong2*)(wpc + 516);
            ulonglong2 nA3 = *(const ulonglong2*)(wpc + 768);
            ulonglong2 nB3 = *(const ulonglong2*)(wpc + 772);

            for (int kk = 0; kk < 32; kk += 4) {
                ulonglong2 wA0 = nA0, wB0 = nB0, wA1 = nA1, wB1 = nB1;
                ulonglong2 wA2 = nA2, wB2 = nB2, wA3 = nA3, wB3 = nB3;
                const float* wn = wpc + (kk + 4) * 256;   // row <= 771 < 832
                nA0 = *(const ulonglong2*)(wn);
                nB0 = *(const ulonglong2*)(wn + 4);
                nA1 = *(const ulonglong2*)(wn + 256);
                nB1 = *(const ulonglong2*)(wn + 260);
                nA2 = *(const ulonglong2*)(wn + 512);
                nB2 = *(const ulonglong2*)(wn + 516);
                nA3 = *(const ulonglong2*)(wn + 768);
                nB3 = *(const ulonglong2*)(wn + 772);
                #pragma unroll
                for (int el = 0; el < 2; ++el) {
                    float4 m4 = *(const float4*)&s.mumd[el][kb2 + kk];
                    unsigned long long d;
                    d = dup2(m4.x); ffma2(ca[el][0], d, wA0.x); ffma2(ca[el][1], d, wA0.y);
                                    ffma2(ca[el][2], d, wB0.x); ffma2(ca[el][3], d, wB0.y);
                    d = dup2(m4.y); ffma2(ca[el][0], d, wA1.x); ffma2(ca[el][1], d, wA1.y);
                                    ffma2(ca[el][2], d, wB1.x); ffma2(ca[el][3], d, wB1.y);
                    d = dup2(m4.z); ffma2(ca[el][0], d, wA2.x); ffma2(ca[el][1], d, wA2.y);
                                    ffma2(ca[el][2], d, wB2.x); ffma2(ca[el][3], d, wB2.y);
                    d = dup2(m4.w); ffma2(ca[el][0], d, wA3.x); ffma2(ca[el][1], d, wA3.y);
                                    ffma2(ca[el][2], d, wB3.x); ffma2(ca[el][3], d, wB3.y);
                }
            }
            #pragma unroll
            for (int el = 0; el < 2; ++el)
                #pragma unroll
                for (int p = 0; p < 4; ++p) {
                    U64 u; u.u = ca[el][p];
                    atomicAdd(&s.cm[el][swz(c0m + 2 * p)],     u.f.x);
                    atomicAdd(&s.cm[el][swz(c0m + 2 * p + 1)], u.f.y);
                }
        }
        __syncthreads();

        // (E) split phase: threads 0-255 epilogue; threads 256-511 scr means + pwS
        if (t < 256) {
            const int c  = t;
            const int cs = swz(c);
            float cm0 = s.cm[0][cs], cm1 = s.cm[1][cs];
            float su0 = 0.f, sd0 = 0.f, su1 = 0.f, sd1 = 0.f;
            #pragma unroll
            for (int e = 0; e < NE; ++e) {
                float2 p0 = s.redP[0][e][c];
                float2 p1 = s.redP[1][e][c];
                float2 p2 = s.redP[2][e][c];
                float2 p3 = s.redP[3][e][c];
                float v0 = fast_tanh(cm0 + p0.x + p1.x + p2.x + p3.x);
                float v1 = fast_tanh(cm1 + p0.y + p1.y + p2.y + p3.y);
                if (!last) {
                    float2 sp = s.svP[e][c];
                    v0 += sp.x; v1 += sp.y;
                }
                s.svP[e][c] = make_float2(v0, v1);
                if (e < 7) { su0 += v0; su1 += v1; } else { sd0 += v0; sd1 += v1; }
            }
            if (!last) {
                s.mumd[0][c]       = su0 * inv7;
                s.mumd[0][256 + c] = sd0 * inv7;
                s.mumd[1][c]       = su1 * inv7;
                s.mumd[1][256 + c] = sd1 * inv7;
                const float* bN = (il == NFB - 1) ? va_b : (s_b + (il + 1) * 256);
                float bv = bN[c];
                s.cm[0][cs] = bv;
                s.cm[1][cs] = bv;
            }
        } else if (!last) {
            for (int idx = t - 256; idx < 896; idx += 256) {
                int dn = idx / 448, q = idx - dn * 448;
                int e = q >> 5, k = q & 31;
                int i0 = dn * 7;
                float s0 = 0.f, s1 = 0.f;
                #pragma unroll
                for (int ii = 0; ii < 7; ++ii) {
                    int off = ((i0 + ii) * 14 + e) * NPVs + k;
                    s0 += s.pv[0][off];
                    s1 += s.pv[1][off];
                }
                s.scrP[idx] = make_float2(s0 * inv7, s1 * inv7);
            }
            if (il + 1 < NFB) {
                for (int idx = t - 256; idx < 1024; idx += 256) s.pwS[idx] = p_w[(il + 1) * 1024 + idx];
                if (t - 256 < 32) s.pbS[t - 256] = p_b[(il + 1) * 32 + (t - 256)];
            }
        }
        __syncthreads();
    }

    // ---------------- Orbitals: el-packed, kh8 split, partials then reduce ----------------
    {
        float2 (*orbRed)[NE][NORB] = reinterpret_cast<float2(*)[NE][NORB]>(s.redP);
        const int kh8 = wid & 7;
        const int eh2 = wid >> 3;
        const int e0  = eh2 * 7;
        const int oc0 = lane * 4;
        if (oc0 < NORB) {
            const float* W = eh2 ? wd_w : wu_w;
            unsigned long long oa[7][4];
            #pragma unroll
            for (int i = 0; i < 7; ++i)
                #pragma unroll
                for (int p = 0; p < 4; ++p) oa[i][p] = 0ull;
            const int kb = kh8 * 32;
            const float* wpo = W + kb * NORB + oc0;
            float4 n0 = *(const float4*)(wpo);
            float4 n1 = *(const float4*)(wpo + NORB);
            float4 n2 = *(const float4*)(wpo + 2 * NORB);
            float4 n3 = *(const float4*)(wpo + 3 * NORB);
            for (int kk = 0; kk < 32; kk += 4) {
                const int k = kb + kk;
                unsigned long long d00 = dup2(n0.x), d01 = dup2(n0.y), d02 = dup2(n0.z), d03 = dup2(n0.w);
                unsigned long long d10 = dup2(n1.x), d11 = dup2(n1.y), d12 = dup2(n1.z), d13 = dup2(n1.w);
                unsigned long long d20 = dup2(n2.x), d21 = dup2(n2.y), d22 = dup2(n2.z), d23 = dup2(n2.w);
                unsigned long long d30 = dup2(n3.x), d31 = dup2(n3.y), d32 = dup2(n3.z), d33 = dup2(n3.w);
                if (kk < 28) {
                    const float* wn = wpo + (kk + 4) * NORB;
                    n0 = *(const float4*)(wn);
                    n1 = *(const float4*)(wn + NORB);
                    n2 = *(const float4*)(wn + 2 * NORB);
                    n3 = *(const float4*)(wn + 3 * NORB);
                }
                #pragma unroll
                for (int i = 0; i < 7; ++i) {
                    ulonglong2 A = *(const ulonglong2*)&s.svP[e0 + i][k];
                    ulonglong2 B = *(const ulonglong2*)&s.svP[e0 + i][k + 2];
                    ffma2(oa[i][0], A.x, d00); ffma2(oa[i][1], A.x, d01);
                    ffma2(oa[i][2], A.x, d02); ffma2(oa[i][3], A.x, d03);
                    ffma2(oa[i][0], A.y, d10); ffma2(oa[i][1], A.y, d11);
                    ffma2(oa[i][2], A.y, d12); ffma2(oa[i][3], A.y, d13);
                    ffma2(oa[i][0], B.x, d20); ffma2(oa[i][1], B.x, d21);
                    ffma2(oa[i][2], B.x, d22); ffma2(oa[i][3], B.x, d23);
                    ffma2(oa[i][0], B.y, d30); ffma2(oa[i][1], B.y, d31);
                    ffma2(oa[i][2], B.y, d32); ffma2(oa[i][3], B.y, d33);
                }
            }
            #pragma unroll
            for (int i = 0; i < 7; ++i) {
                U64 u0, u1, u2, u3;
                u0.u = oa[i][0]; u1.u = oa[i][1]; u2.u = oa[i][2]; u3.u = oa[i][3];
                orbRed[kh8][e0 + i][oc0 + 0] = u0.f;
                orbRed[kh8][e0 + i][oc0 + 1] = u1.f;
                orbRed[kh8][e0 + i][oc0 + 2] = u2.f;
                orbRed[kh8][e0 + i][oc0 + 3] = u3.f;
            }
        }
    }
    __syncthreads();
    {
        float2 (*orbRed)[NE][NORB] = reinterpret_cast<float2(*)[NE][NORB]>(s.redP);
        for (int idx = t; idx < NE * NORB; idx += 512) {
            int e = idx / NORB, o = idx - e * NORB;
            float bv = (e < 7) ? wu_b[o] : wd_b[o];
            float v0 = bv, v1 = bv;
            #pragma unroll
            for (int ss = 0; ss < 8; ++ss) {
                float2 p = orbRed[ss][e][o];
                v0 += p.x; v1 += p.y;
            }
            int og = e * NORB + swzo(o);
            s.pv[0][og] = v0 * s.env[0][e];
            s.pv[1][og] = v1 * s.env[1][e];
        }
    }
    __syncthreads();

    // ---------------- 2 x 32 slogdets of 7x7 ----------------
    if (t < 64) {
        const int el = t >> 5, tt = t & 31;
        const int sp = tt >> 4, d = tt & 15;
        float m[7][7];
        #pragma unroll
        for (int j = 0; j < 7; ++j) {
            int og = swzo(j * 16 + d);
            #pragma unroll
            for (int i = 0; i < 7; ++i)
                m[j][i] = s.pv[el][(sp * 7 + i) * NORB + og];
        }
        float ld = 0.f, sg = 1.f;
        #pragma unroll
        for (int col = 0; col < 7; ++col) {
            #pragma unroll
            for (int rr = col + 1; rr < 7; ++rr) {
                if (fabsf(m[rr][col]) > fabsf(m[col][col])) {
                    sg = -sg;
                    #pragma unroll
                    for (int cc = 0; cc < 7; ++cc) {
                        float tmp = m[col][cc]; m[col][cc] = m[rr][cc]; m[rr][cc] = tmp;
                    }
                }
            }
            float piv = m[col][col];
            sg = (piv < 0.f) ? -sg : sg;
            ld += __logf(fabsf(piv));
            float inv = 1.f / piv;
            #pragma unroll
            for (int rr = col + 1; rr < 7; ++rr) {
                float f = m[rr][col] * inv;
                #pragma unroll
                for (int cc = col + 1; cc < 7; ++cc)
                    m[rr][cc] -= f * m[col][cc];
            }
        }
        s.ldet[el][tt] = ld;
        s.sgn[el][tt] = sg;
    }
    __syncthreads();

    if (t < 2 && (b0 + t) < nb) {
        const int el = t;
        float l[16], mx = -3.4e38f;
        #pragma unroll
        for (int d = 0; d < 16; ++d) {
            l[d] = s.ldet[el][d] + s.ldet[el][16 + d];
            mx = fmaxf(mx, l[d]);
        }
        float psi = 0.f;
        #pragma unroll
        for (int d = 0; d < 16; ++d)
            psi += s.sgn[el][d] * s.sgn[el][16 + d] * __expf(l[d] - mx) * wf_w[d];
        out[b0 + el] = __logf(fabsf(psi)) + mx;
    }
}

extern "C" void kernel_launch(void* const* d_in, const int* in_sizes, int n_in,
                              void* d_out, int out_size)
{
    const float* r    = (const float*)d_in[0];
    const float* s_w0 = (const float*)d_in[1];
    const float* s_b0 = (const float*)d_in[2];
    const float* s_w  = (const float*)d_in[3];
    const float* s_b  = (const float*)d_in[4];
    const float* p_w0 = (const float*)d_in[5];
    const float* p_b0 = (const float*)d_in[6];
    const float* p_w  = (const float*)d_in[7];
    const float* p_b  = (const float*)d_in[8];
    const float* va_w = (const float*)d_in[9];
    const float* va_b = (const float*)d_in[10];
    const float* wu_w = (const float*)d_in[11];
    const float* wu_b = (const float*)d_in[12];
    const float* wd_w = (const float*)d_in[13];
    const float* wd_b = (const float*)d_in[14];
    const float* wf_w = (const float*)d_in[15];

    const int nb  = in_sizes[0] / (14 * 3);
    const int nb2 = (nb + 1) / 2;
    const int smem = (int)sizeof(Smem);
    cudaFuncSetAttribute(ansatz_kernel, cudaFuncAttributeMaxDynamicSharedMemorySize, smem);
    ansatz_kernel<<<nb2, 512, smem>>>(r, s_w0, s_b0, s_w, s_b, p_w0, p_b0, p_w, p_b,
                                      va_w, va_b, wu_w, wu_b, wd_w, wd_b, wf_w,
                                      (float*)d_out, nb);
}

// round 16
// speedup vs baseline: 1.0638x; 1.0638x over previous
#include <cuda_runtime.h>
#include <math.h>

#define NE    14
#define NSV   256
#define NPVs  33
#define NPAIR 196
#define NORB  112
#define NFB   3

struct __align__(16) Smem {
    float2 svP[NE][NSV];         // packed (el0, el1)
    float  pv[2][NPAIR * NPVs];  // unpacked pair stream; reused as orbm
    float2 redP[4][NE][NSV];     // packed k-split partials; orbital reuses as [8][NE][NORB]
    float2 scrP[896];            // packed ext means; layer0 pin via float* view
    float  mumd[2][512];
    float  cm[2][NSV];
    float  pwS[1024];
    float  pbS[32];
    float  m0P[2][16];
    float  sin8[2][NE][8];
    float  env[2][NE];
    float  rl[2][NE][3];
    float  ldet[2][32];
    float  sgn[2][32];
};

union U64 { unsigned long long u; float2 f; };

__device__ __forceinline__ void ffma2(unsigned long long &d, unsigned long long a, unsigned long long b) {
    asm("fma.rn.f32x2 %0, %1, %2, %0;" : "+l"(d) : "l"(a), "l"(b));
}
__device__ __forceinline__ unsigned long long dup2(float x) {
    unsigned long long r;
    asm("mov.b64 %0, {%1, %1};" : "=l"(r) : "f"(x));
    return r;
}
__device__ __forceinline__ int swz(int c)  { return c ^ (c >> 5); }
__device__ __forceinline__ int swzo(int o) { return o ^ (o >> 5); }

__device__ __forceinline__ float fast_tanh(float x) {
    float e = __expf(2.0f * x);
    return 1.0f - __fdividef(2.0f, e + 1.0f);
}

__global__ void __launch_bounds__(512, 1)
ansatz_kernel(const float* __restrict__ r,
              const float* __restrict__ s_w0, const float* __restrict__ s_b0,
              const float* __restrict__ s_w,  const float* __restrict__ s_b,
              const float* __restrict__ p_w0, const float* __restrict__ p_b0,
              const float* __restrict__ p_w,  const float* __restrict__ p_b,
              const float* __restrict__ va_w, const float* __restrict__ va_b,
              const float* __restrict__ wu_w, const float* __restrict__ wu_b,
              const float* __restrict__ wd_w, const float* __restrict__ wd_b,
              const float* __restrict__ wf_w,
              float* __restrict__ out, int nb)
{
    extern __shared__ char smem_raw[];
    Smem& s = *reinterpret_cast<Smem*>(smem_raw);

    const int t    = threadIdx.x;
    const int lane = t & 31;
    const int wid  = t >> 5;
    const int b0   = blockIdx.x * 2;
    const float inv7 = 1.0f / 7.0f;

    const int tel = t >> 8;
    const int tc  = t & 255;

    float* scrF = (float*)s.scrP;   // layer0 view [el*896 + ...]

    // ---------------- Phase 0: geometry ----------------
    for (int q = t; q < 2 * NE * 3; q += 512) {
        int el = q / (NE * 3);
        int bel = b0 + el; if (bel >= nb) bel = nb - 1;
        ((float*)s.rl[el])[q - el * (NE * 3)] = r[bel * (NE * 3) + (q - el * (NE * 3))];
    }
    __syncthreads();

    if (t < 2 * NE) {
        int el = t / NE, e = t - el * NE;
        float x = s.rl[el][e][0], y = s.rl[el][e][1], z = s.rl[el][e][2];
        float ev = 0.f;
        #pragma unroll
        for (int a = 0; a < 2; ++a) {
            float dz = z - (a ? 1.4f : 0.0f);
            float len = sqrtf(x * x + y * y + dz * dz);
            s.sin8[el][e][a * 4 + 0] = x;
            s.sin8[el][e][a * 4 + 1] = y;
            s.sin8[el][e][a * 4 + 2] = dz;
            s.sin8[el][e][a * 4 + 3] = len;
            ev += __expf(-len);
        }
        s.env[el][e] = ev;
    }
    if (t < 2 * NPAIR) {
        int el = t / NPAIR, pr = t - el * NPAIR;
        int i = pr / 14, j = pr - i * 14;
        float dx = s.rl[el][j][0] - s.rl[el][i][0];
        float dy = s.rl[el][j][1] - s.rl[el][i][1];
        float dz = s.rl[el][j][2] - s.rl[el][i][2];
        float ax = dx, ay = dy, az = dz;
        if (i == j) { ax += 1.f; ay += 1.f; az += 1.f; }
        float len = sqrtf(ax * ax + ay * ay + az * az);
        scrF[el * 896 + pr * 4 + 0] = dx; scrF[el * 896 + pr * 4 + 1] = dy;
        scrF[el * 896 + pr * 4 + 2] = dz; scrF[el * 896 + pr * 4 + 3] = len;
    }
    __syncthreads();

    if (t < 32) {
        int el = t >> 4, q = t & 15;
        int k = q & 7, half = q >> 3;
        float su = 0.f;
        #pragma unroll
        for (int e = 0; e < 7; ++e) su += s.sin8[el][half * 7 + e][k];
        s.m0P[el][half * 8 + k] = su * inv7;
    }
    if (t >= 64 && t < 64 + 224) {
        int q2 = t - 64;
        int el = q2 / 112, q = q2 - el * 112;
        int dn = (q >= 56) ? 1 : 0;
        int qq = q - dn * 56;
        int e = qq >> 2, k = qq & 3;
        int i0 = dn ? 7 : 0;
        float su = 0.f;
        #pragma unroll
        for (int ii = 0; ii < 7; ++ii) su += scrF[el * 896 + ((i0 + ii) * 14 + e) * 4 + k];
        scrF[el * 896 + 784 + dn * 56 + e * 4 + k] = su * inv7;
    }
    __syncthreads();

    // ---------------- Layer 0 (fused: svP + mumd + cm init) ----------------
    {
        float pnew[32];
        const bool prow = (t < 2 * NPAIR);
        int pel = 0, pr = 0;
        if (prow) {
            pel = t / NPAIR; pr = t - pel * NPAIR;
            const float* pin = scrF + pel * 896 + pr * 4;
            float r0 = pin[0], r1 = pin[1], r2 = pin[2], r3 = pin[3];
            #pragma unroll
            for (int c2 = 0; c2 < 32; ++c2) {
                float v = p_b0[c2]
                        + r0 * p_w0[0 * 32 + c2] + r1 * p_w0[1 * 32 + c2]
                        + r2 * p_w0[2 * 32 + c2] + r3 * p_w0[3 * 32 + c2];
                pnew[c2] = fast_tanh(v);
            }
        }
        float cm0 = s_b0[tc];
        #pragma unroll
        for (int k = 0; k < 8; ++k)
            cm0 += s.m0P[tel][k] * s_w0[(8 + k) * 256 + tc] + s.m0P[tel][8 + k] * s_w0[(16 + k) * 256 + tc];
        float acc[NE];
        #pragma unroll
        for (int e = 0; e < NE; ++e) acc[e] = cm0;
        #pragma unroll
        for (int k = 0; k < 8; ++k) {
            float w = s_w0[k * 256 + tc];
            #pragma unroll
            for (int e = 0; e < NE; ++e) acc[e] += s.sin8[tel][e][k] * w;
        }
        const float* pu0 = scrF + tel * 896 + 784;
        const float* pd0 = scrF + tel * 896 + 840;
        #pragma unroll
        for (int k = 0; k < 4; ++k) {
            float wuv = s_w0[(24 + k) * 256 + tc];
            float wdv = s_w0[(28 + k) * 256 + tc];
            #pragma unroll
            for (int e = 0; e < NE; ++e)
                acc[e] += pu0[e * 4 + k] * wuv + pd0[e * 4 + k] * wdv;
        }
        float su = 0.f, sd = 0.f;
        #pragma unroll
        for (int e = 0; e < NE; ++e) {
            float v = fast_tanh(acc[e]);
            ((float*)&s.svP[e][tc])[tel] = v;
            if (e < 7) su += v; else sd += v;
        }
        s.mumd[tel][tc]       = su * inv7;
        s.mumd[tel][256 + tc] = sd * inv7;
        s.cm[tel][swz(tc)]    = s_b[tc];
        if (prow) {
            #pragma unroll
            for (int c2 = 0; c2 < 32; ++c2) s.pv[pel][pr * NPVs + c2] = pnew[c2];
        }
    }
    __syncthreads();

    // ---------------- prep il=0: packed scr means + pwS ----------------
    for (int idx = t; idx < 896; idx += 512) {
        int dn = idx / 448, q = idx - dn * 448;
        int e = q >> 5, k = q & 31;
        int i0 = dn * 7;
        float s0 = 0.f, s1 = 0.f;
        #pragma unroll
        for (int ii = 0; ii < 7; ++ii) {
            int off = ((i0 + ii) * 14 + e) * NPVs + k;
            s0 += s.pv[0][off];
            s1 += s.pv[1][off];
        }
        s.scrP[idx] = make_float2(s0 * inv7, s1 * inv7);
    }
    #pragma unroll
    for (int idx = t; idx < 1024; idx += 512) s.pwS[idx] = p_w[idx];
    if (t < 32) s.pbS[t] = p_b[t];
    __syncthreads();

    // ---------------- FB layers + final va ----------------
    for (int il = 0; il <= NFB; ++il) {
        const bool last = (il == NFB);
        const float* WL = last ? va_w : (s_w + il * (832 * 256));

        // (b) pair GEMM — one thread = one pair row, both elements share weight broadcasts
        if (!last && t < NPAIR) {
            const int pr = t;
            unsigned long long o0[16], o1[16];
            const ulonglong2* pb2 = (const ulonglong2*)s.pbS;
            #pragma unroll
            for (int q = 0; q < 8; ++q) {
                ulonglong2 bv = pb2[q];
                o0[2 * q] = bv.x; o0[2 * q + 1] = bv.y;
                o1[2 * q] = bv.x; o1[2 * q + 1] = bv.y;
            }
            #pragma unroll 4
            for (int k = 0; k < 32; ++k) {
                unsigned long long r0 = dup2(s.pv[0][pr * NPVs + k]);
                unsigned long long r1 = dup2(s.pv[1][pr * NPVs + k]);
                const ulonglong2* w2 = (const ulonglong2*)(s.pwS + k * 32);
                #pragma unroll
                for (int q = 0; q < 8; ++q) {
                    ulonglong2 wv = w2[q];
                    ffma2(o0[2 * q],     r0, wv.x);
                    ffma2(o0[2 * q + 1], r0, wv.y);
                    ffma2(o1[2 * q],     r1, wv.x);
                    ffma2(o1[2 * q + 1], r1, wv.y);
                }
            }
            #pragma unroll
            for (int q = 0; q < 16; ++q) {
                U64 u0; u0.u = o0[q];
                U64 u1; u1.u = o1[q];
                s.pv[0][pr * NPVs + 2 * q]     = fast_tanh(u0.f.x) + s.pv[0][pr * NPVs + 2 * q];
                s.pv[0][pr * NPVs + 2 * q + 1] = fast_tanh(u0.f.y) + s.pv[0][pr * NPVs + 2 * q + 1];
                s.pv[1][pr * NPVs + 2 * q]     = fast_tanh(u1.f.x) + s.pv[1][pr * NPVs + 2 * q];
                s.pv[1][pr * NPVs + 2 * q + 1] = fast_tanh(u1.f.y) + s.pv[1][pr * NPVs + 2 * q + 1];
            }
        }

        // (c) cm rank-1 GEMM, pipelined
        {
            const int kb2 = wid * 32;
            const int c0m = lane * 8;
            unsigned long long ca[2][4];
            #pragma unroll
            for (int el = 0; el < 2; ++el)
                #pragma unroll
                for (int p = 0; p < 4; ++p) ca[el][p] = 0ull;

            const float* wpc = WL + (256 + kb2) * 256 + c0m;
            ulonglong2 nA0 = *(const ulonglong2*)(wpc);
            ulonglong2 nB0 = *(const ulonglong2*)(wpc + 4);
            ulonglong2 nA1 = *(const ulonglong2*)(wpc + 256);
            ulonglong2 nB1 = *(const ulonglong2*)(wpc + 260);
            ulonglong2 nA2 = *(const ulonglong2*)(wpc + 512);
            ulonglong2 nB2 = *(const ulonglong2*)(wpc + 516);
            ulonglong2 nA3 = *(const ulonglong2*)(wpc + 768);
            ulonglong2 nB3 = *(const ulonglong2*)(wpc + 772);

            for (int kk = 0; kk < 32; kk += 4) {
                ulonglong2 wA0 = nA0, wB0 = nB0, wA1 = nA1, wB1 = nB1;
                ulonglong2 wA2 = nA2, wB2 = nB2, wA3 = nA3, wB3 = nB3;
                const float* wn = wpc + (kk + 4) * 256;   // row <= 771 < 832
                nA0 = *(const ulonglong2*)(wn);
                nB0 = *(const ulonglong2*)(wn + 4);
                nA1 = *(const ulonglong2*)(wn + 256);
                nB1 = *(const ulonglong2*)(wn + 260);
                nA2 = *(const ulonglong2*)(wn + 512);
                nB2 = *(const ulonglong2*)(wn + 516);
                nA3 = *(const ulonglong2*)(wn + 768);
                nB3 = *(const ulonglong2*)(wn + 772);
                #pragma unroll
                for (int el = 0; el < 2; ++el) {
                    float4 m4 = *(const float4*)&s.mumd[el][kb2 + kk];
                    unsigned long long d;
                    d = dup2(m4.x); ffma2(ca[el][0], d, wA0.x); ffma2(ca[el][1], d, wA0.y);
                                    ffma2(ca[el][2], d, wB0.x); ffma2(ca[el][3], d, wB0.y);
                    d = dup2(m4.y); ffma2(ca[el][0], d, wA1.x); ffma2(ca[el][1], d, wA1.y);
                                    ffma2(ca[el][2], d, wB1.x); ffma2(ca[el][3], d, wB1.y);
                    d = dup2(m4.z); ffma2(ca[el][0], d, wA2.x); ffma2(ca[el][1], d, wA2.y);
                                    ffma2(ca[el][2], d, wB2.x); ffma2(ca[el][3], d, wB2.y);
                    d = dup2(m4.w); ffma2(ca[el][0], d, wA3.x); ffma2(ca[el][1], d, wA3.y);
                                    ffma2(ca[el][2], d, wB3.x); ffma2(ca[el][3], d, wB3.y);
                }
            }
            #pragma unroll
            for (int el = 0; el < 2; ++el)
                #pragma unroll
                for (int p = 0; p < 4; ++p) {
                    U64 u; u.u = ca[el][p];
                    atomicAdd(&s.cm[el][swz(c0m + 2 * p)],     u.f.x);
                    atomicAdd(&s.cm[el][swz(c0m + 2 * p + 1)], u.f.y);
                }
        }

        // (d) main electron GEMM: el-packed activations, weight-dups only
        {
            const int kh  = wid & 3;
            const int ch  = (wid >> 2) & 1;
            const int eh2 = wid >> 3;
            const int e0  = eh2 * 7;
            const int c0  = ch * 128 + lane * 4;
            unsigned long long acc[7][4];
            #pragma unroll
            for (int i = 0; i < 7; ++i)
                #pragma unroll
                for (int c = 0; c < 4; ++c) acc[i][c] = 0ull;

            const int kb = kh * 64;
            const float* wpm = WL + kb * 256 + c0;
            float4 n0 = *(const float4*)(wpm);
            float4 n1 = *(const float4*)(wpm + 256);
            float4 n2 = *(const float4*)(wpm + 512);
            float4 n3 = *(const float4*)(wpm + 768);

            for (int kk = 0; kk < 64; kk += 4) {
                const int k = kb + kk;
                unsigned long long d00 = dup2(n0.x), d01 = dup2(n0.y), d02 = dup2(n0.z), d03 = dup2(n0.w);
                unsigned long long d10 = dup2(n1.x), d11 = dup2(n1.y), d12 = dup2(n1.z), d13 = dup2(n1.w);
                unsigned long long d20 = dup2(n2.x), d21 = dup2(n2.y), d22 = dup2(n2.z), d23 = dup2(n2.w);
                unsigned long long d30 = dup2(n3.x), d31 = dup2(n3.y), d32 = dup2(n3.z), d33 = dup2(n3.w);
                const float* wn = wpm + (kk + 4) * 256;   // row <= kb+67 <= 259 < 832
                n0 = *(const float4*)(wn);
                n1 = *(const float4*)(wn + 256);
                n2 = *(const float4*)(wn + 512);
                n3 = *(const float4*)(wn + 768);
                #pragma unroll
                for (int i = 0; i < 7; ++i) {
                    ulonglong2 A = *(const ulonglong2*)&s.svP[e0 + i][k];
                    ulonglong2 B = *(const ulonglong2*)&s.svP[e0 + i][k + 2];
                    ffma2(acc[i][0], A.x, d00); ffma2(acc[i][1], A.x, d01);
                    ffma2(acc[i][2], A.x, d02); ffma2(acc[i][3], A.x, d03);
                    ffma2(acc[i][0], A.y, d10); ffma2(acc[i][1], A.y, d11);
                    ffma2(acc[i][2], A.y, d12); ffma2(acc[i][3], A.y, d13);
                    ffma2(acc[i][0], B.x, d20); ffma2(acc[i][1], B.x, d21);
                    ffma2(acc[i][2], B.x, d22); ffma2(acc[i][3], B.x, d23);
                    ffma2(acc[i][0], B.y, d30); ffma2(acc[i][1], B.y, d31);
                    ffma2(acc[i][2], B.y, d32); ffma2(acc[i][3], B.y, d33);
                }
            }
            // ext rows: kh handles k in [kh*8, kh*8+8)
            #pragma unroll
            for (int blk = 0; blk < 2; ++blk) {
                const int rowb = 768 + blk * 32;
                const int scrb = blk * 448;
                #pragma unroll
                for (int kk = 0; kk < 8; kk += 4) {
                    const int k = kh * 8 + kk;
                    const float* wp = WL + (rowb + k) * 256 + c0;
                    float4 w0 = *(const float4*)(wp);
                    float4 w1 = *(const float4*)(wp + 256);
                    float4 w2 = *(const float4*)(wp + 512);
                    float4 w3 = *(const float4*)(wp + 768);
                    unsigned long long d00 = dup2(w0.x), d01 = dup2(w0.y), d02 = dup2(w0.z), d03 = dup2(w0.w);
                    unsigned long long d10 = dup2(w1.x), d11 = dup2(w1.y), d12 = dup2(w1.z), d13 = dup2(w1.w);
                    unsigned long long d20 = dup2(w2.x), d21 = dup2(w2.y), d22 = dup2(w2.z), d23 = dup2(w2.w);
                    unsigned long long d30 = dup2(w3.x), d31 = dup2(w3.y), d32 = dup2(w3.z), d33 = dup2(w3.w);
                    #pragma unroll
                    for (int i = 0; i < 7; ++i) {
                        const float2* sp = &s.scrP[scrb + (e0 + i) * 32 + k];
                        ulonglong2 A = *(const ulonglong2*)(sp);
                        ulonglong2 B = *(const ulonglong2*)(sp + 2);
                        ffma2(acc[i][0], A.x, d00); ffma2(acc[i][1], A.x, d01);
                        ffma2(acc[i][2], A.x, d02); ffma2(acc[i][3], A.x, d03);
                        ffma2(acc[i][0], A.y, d10); ffma2(acc[i][1], A.y, d11);
                        ffma2(acc[i][2], A.y, d12); ffma2(acc[i][3], A.y, d13);
                        ffma2(acc[i][0], B.x, d20); ffma2(acc[i][1], B.x, d21);
                        ffma2(acc[i][2], B.x, d22); ffma2(acc[i][3], B.x, d23);
                        ffma2(acc[i][0], B.y, d30); ffma2(acc[i][1], B.y, d31);
                        ffma2(acc[i][2], B.y, d32); ffma2(acc[i][3], B.y, d33);
                    }
                }
            }
            // store packed partials
            #pragma unroll
            for (int i = 0; i < 7; ++i) {
                U64 u0, u1, u2, u3;
                u0.u = acc[i][0]; u1.u = acc[i][1]; u2.u = acc[i][2]; u3.u = acc[i][3];
                *reinterpret_cast<float4*>(&s.redP[kh][e0 + i][c0])     = make_float4(u0.f.x, u0.f.y, u1.f.x, u1.f.y);
                *reinterpret_cast<float4*>(&s.redP[kh][e0 + i][c0 + 2]) = make_float4(u2.f.x, u2.f.y, u3.f.x, u3.f.y);
            }
        }
        __syncthreads();

        // (E) split phase: threads 0-255 epilogue; threads 256-511 scr means + pwS
        if (t < 256) {
            const int c  = t;
            const int cs = swz(c);
            float cm0 = s.cm[0][cs], cm1 = s.cm[1][cs];
            float su0 = 0.f, sd0 = 0.f, su1 = 0.f, sd1 = 0.f;
            #pragma unroll
            for (int e = 0; e < NE; ++e) {
                float2 p0 = s.redP[0][e][c];
                float2 p1 = s.redP[1][e][c];
                float2 p2 = s.redP[2][e][c];
                float2 p3 = s.redP[3][e][c];
                float v0 = fast_tanh(cm0 + p0.x + p1.x + p2.x + p3.x);
                float v1 = fast_tanh(cm1 + p0.y + p1.y + p2.y + p3.y);
                if (!last) {
                    float2 sp = s.svP[e][c];
                    v0 += sp.x; v1 += sp.y;
                }
                s.svP[e][c] = make_float2(v0, v1);
                if (e < 7) { su0 += v0; su1 += v1; } else { sd0 += v0; sd1 += v1; }
            }
            if (!last) {
                s.mumd[0][c]       = su0 * inv7;
                s.mumd[0][256 + c] = sd0 * inv7;
                s.mumd[1][c]       = su1 * inv7;
                s.mumd[1][256 + c] = sd1 * inv7;
                const float* bN = (il == NFB - 1) ? va_b : (s_b + (il + 1) * 256);
                float bv = bN[c];
                s.cm[0][cs] = bv;
                s.cm[1][cs] = bv;
            }
        } else if (!last) {
            for (int idx = t - 256; idx < 896; idx += 256) {
                int dn = idx / 448, q = idx - dn * 448;
                int e = q >> 5, k = q & 31;
                int i0 = dn * 7;
                float s0 = 0.f, s1 = 0.f;
                #pragma unroll
                for (int ii = 0; ii < 7; ++ii) {
                    int off = ((i0 + ii) * 14 + e) * NPVs + k;
                    s0 += s.pv[0][off];
                    s1 += s.pv[1][off];
                }
                s.scrP[idx] = make_float2(s0 * inv7, s1 * inv7);
            }
            if (il + 1 < NFB) {
                for (int idx = t - 256; idx < 1024; idx += 256) s.pwS[idx] = p_w[(il + 1) * 1024 + idx];
                if (t - 256 < 32) s.pbS[t - 256] = p_b[(il + 1) * 32 + (t - 256)];
            }
        }
        __syncthreads();
    }

    // ---------------- Orbitals: el-packed, kh8 split, partials then reduce ----------------
    {
        float2 (*orbRed)[NE][NORB] = reinterpret_cast<float2(*)[NE][NORB]>(s.redP);
        const int kh8 = wid & 7;
        const int eh2 = wid >> 3;
        const int e0  = eh2 * 7;
        const int oc0 = lane * 4;
        if (oc0 < NORB) {
            const float* W = eh2 ? wd_w : wu_w;
            unsigned long long oa[7][4];
            #pragma unroll
            for (int i = 0; i < 7; ++i)
                #pragma unroll
                for (int p = 0; p < 4; ++p) oa[i][p] = 0ull;
            const int kb = kh8 * 32;
            const float* wpo = W + kb * NORB + oc0;
            float4 n0 = *(const float4*)(wpo);
            float4 n1 = *(const float4*)(wpo + NORB);
            float4 n2 = *(const float4*)(wpo + 2 * NORB);
            float4 n3 = *(const float4*)(wpo + 3 * NORB);
            for (int kk = 0; kk < 32; kk += 4) {
                const int k = kb + kk;
                unsigned long long d00 = dup2(n0.x), d01 = dup2(n0.y), d02 = dup2(n0.z), d03 = dup2(n0.w);
                unsigned long long d10 = dup2(n1.x), d11 = dup2(n1.y), d12 = dup2(n1.z), d13 = dup2(n1.w);
                unsigned long long d20 = dup2(n2.x), d21 = dup2(n2.y), d22 = dup2(n2.z), d23 = dup2(n2.w);
                unsigned long long d30 = dup2(n3.x), d31 = dup2(n3.y), d32 = dup2(n3.z), d33 = dup2(n3.w);
                if (kk < 28) {
                    const float* wn = wpo + (kk + 4) * NORB;
                    n0 = *(const float4*)(wn);
                    n1 = *(const float4*)(wn + NORB);
                    n2 = *(const float4*)(wn + 2 * NORB);
                    n3 = *(const float4*)(wn + 3 * NORB);
                }
                #pragma unroll
                for (int i = 0; i < 7; ++i) {
                    ulonglong2 A = *(const ulonglong2*)&s.svP[e0 + i][k];
                    ulonglong2 B = *(const ulonglong2*)&s.svP[e0 + i][k + 2];
                    ffma2(oa[i][0], A.x, d00); ffma2(oa[i][1], A.x, d01);
                    ffma2(oa[i][2], A.x, d02); ffma2(oa[i][3], A.x, d03);
                    ffma2(oa[i][0], A.y, d10); ffma2(oa[i][1], A.y, d11);
                    ffma2(oa[i][2], A.y, d12); ffma2(oa[i][3], A.y, d13);
                    ffma2(oa[i][0], B.x, d20); ffma2(oa[i][1], B.x, d21);
                    ffma2(oa[i][2], B.x, d22); ffma2(oa[i][3], B.x, d23);
                    ffma2(oa[i][0], B.y, d30); ffma2(oa[i][1], B.y, d31);
                    ffma2(oa[i][2], B.y, d32); ffma2(oa[i][3], B.y, d33);
                }
            }
            #pragma unroll
            for (int i = 0; i < 7; ++i) {
                U64 u0, u1, u2, u3;
                u0.u = oa[i][0]; u1.u = oa[i][1]; u2.u = oa[i][2]; u3.u = oa[i][3];
                orbRed[kh8][e0 + i][oc0 + 0] = u0.f;
                orbRed[kh8][e0 + i][oc0 + 1] = u1.f;
                orbRed[kh8][e0 + i][oc0 + 2] = u2.f;
                orbRed[kh8][e0 + i][oc0 + 3] = u3.f;
            }
        }
    }
    __syncthreads();
    {
        float2 (*orbRed)[NE][NORB] = reinterpret_cast<float2(*)[NE][NORB]>(s.redP);
        for (int idx = t; idx < NE * NORB; idx += 512) {
            int e = idx / NORB, o = idx - e * NORB;
            float bv = (e < 7) ? wu_b[o] : wd_b[o];
            float v0 = bv, v1 = bv;
            #pragma unroll
            for (int ss = 0; ss < 8; ++ss) {
                float2 p = orbRed[ss][e][o];
                v0 += p.x; v1 += p.y;
            }
            int og = e * NORB + swzo(o);
            s.pv[0][og] = v0 * s.env[0][e];
            s.pv[1][og] = v1 * s.env[1][e];
        }
    }
    __syncthreads();

    // ---------------- 2 x 32 slogdets of 7x7 ----------------
    if (t < 64) {
        const int el = t >> 5, tt = t & 31;
        const int sp = tt >> 4, d = tt & 15;
        float m[7][7];
        #pragma unroll
        for (int j = 0; j < 7; ++j) {
            int og = swzo(j * 16 + d);
            #pragma unroll
            for (int i = 0; i < 7; ++i)
                m[j][i] = s.pv[el][(sp * 7 + i) * NORB + og];
        }
        float ld = 0.f, sg = 1.f;
        #pragma unroll
        for (int col = 0; col < 7; ++col) {
            #pragma unroll
            for (int rr = col + 1; rr < 7; ++rr) {
                if (fabsf(m[rr][col]) > fabsf(m[col][col])) {
                    sg = -sg;
                    #pragma unroll
                    for (int cc = 0; cc < 7; ++cc) {
                        float tmp = m[col][cc]; m[col][cc] = m[rr][cc]; m[rr][cc] = tmp;
                    }
                }
            }
            float piv = m[col][col];
            sg = (piv < 0.f) ? -sg : sg;
            ld += __logf(fabsf(piv));
            float inv = 1.f / piv;
            #pragma unroll
            for (int rr = col + 1; rr < 7; ++rr) {
                float f = m[rr][col] * inv;
                #pragma unroll
                for (int cc = col + 1; cc < 7; ++cc)
                    m[rr][cc] -= f * m[col][cc];
            }
        }
        s.ldet[el][tt] = ld;
        s.sgn[el][tt] = sg;
    }
    __syncthreads();

    if (t < 2 && (b0 + t) < nb) {
        const int el = t;
        float l[16], mx = -3.4e38f;
        #pragma unroll
        for (int d = 0; d < 16; ++d) {
            l[d] = s.ldet[el][d] + s.ldet[el][16 + d];
            mx = fmaxf(mx, l[d]);
        }
        float psi = 0.f;
        #pragma unroll
        for (int d = 0; d < 16; ++d)
            psi += s.sgn[el][d] * s.sgn[el][16 + d] * __expf(l[d] - mx) * wf_w[d];
        out[b0 + el] = __logf(fabsf(psi)) + mx;
    }
}

extern "C" void kernel_launch(void* const* d_in, const int* in_sizes, int n_in,
                              void* d_out, int out_size)
{
    const float* r    = (const float*)d_in[0];
    const float* s_w0 = (const float*)d_in[1];
    const float* s_b0 = (const float*)d_in[2];
    const float* s_w  = (const float*)d_in[3];
    const float* s_b  = (const float*)d_in[4];
    const float* p_w0 = (const float*)d_in[5];
    const float* p_b0 = (const float*)d_in[6];
    const float* p_w  = (const float*)d_in[7];
    const float* p_b  = (const float*)d_in[8];
    const float* va_w = (const float*)d_in[9];
    const float* va_b = (const float*)d_in[10];
    const float* wu_w = (const float*)d_in[11];
    const float* wu_b = (const float*)d_in[12];
    const float* wd_w = (const float*)d_in[13];
    const float* wd_b = (const float*)d_in[14];
    const float* wf_w = (const float*)d_in[15];

    const int nb  = in_sizes[0] / (14 * 3);
    const int nb2 = (nb + 1) / 2;
    const int smem = (int)sizeof(Smem);
    cudaFuncSetAttribute(ansatz_kernel, cudaFuncAttributeMaxDynamicSharedMemorySize, smem);
    ansatz_kernel<<<nb2, 512, smem>>>(r, s_w0, s_b0, s_w, s_b, p_w0, p_b0, p_w, p_b,
                                      va_w, va_b, wu_w, wu_b, wd_w, wd_b, wf_w,
                                      (float*)d_out, nb);
}